// round 2
// baseline (speedup 1.0000x reference)
#include <cuda_runtime.h>

// LocalAggregationLoss
//   codes:        [1024, 128] fp32
//   memory_bank:  [1000000, 128] fp32 (rows unit-norm)
//   idx_background, idx_close: [1024, 200] int32 (JAX x64 disabled) or int64
//   out:          [1024] fp32 = log(sum exp(dot(bank[idx_bg], v)/T))
//                             - log(sum exp(dot(bank[idx_cl], v)/T))
// v = codes row L2-normalized.

#define DIM    128
#define KNEI   200
#define TINV   (1.0f / 0.07f)
#define NWARP  8
#define N_BANK 1000000LL

// 0 = indices are int32, 1 = indices are int64
__device__ int g_idx_is64;

__global__ void detect_idx_dtype(const void* idx_raw)
{
    const long long* p = (const long long*)idx_raw;
    int is64 = 1;
    // If data is really int32, an int64 view packs two indices:
    // val = lo + (hi << 32), hi != 0 with overwhelming probability.
    for (int i = 0; i < 64; ++i) {
        long long v = p[i];
        if (v < 0 || v >= N_BANK) { is64 = 0; break; }
    }
    g_idx_is64 = is64;
}

template <typename IdxT>
__device__ __forceinline__ void accumulate(const float* __restrict__ bank,
                                           const IdxT* __restrict__ ibg,
                                           const IdxT* __restrict__ icl,
                                           float4 vv, int wid, int lane,
                                           float& s1, float& s2)
{
    for (int r = wid; r < KNEI; r += NWARP) {
        const long long i1 = (long long)ibg[r];  // broadcast
        const long long i2 = (long long)icl[r];

        // two independent 512B coalesced gathers in flight per warp
        const float4 a = *reinterpret_cast<const float4*>(
            bank + i1 * DIM + lane * 4);
        const float4 g = *reinterpret_cast<const float4*>(
            bank + i2 * DIM + lane * 4);

        float d1 = a.x * vv.x + a.y * vv.y + a.z * vv.z + a.w * vv.w;
        float d2 = g.x * vv.x + g.y * vv.y + g.z * vv.z + g.w * vv.w;

        #pragma unroll
        for (int o = 16; o; o >>= 1) {
            d1 += __shfl_xor_sync(0xffffffffu, d1, o);
            d2 += __shfl_xor_sync(0xffffffffu, d2, o);
        }
        s1 += expf(d1 * TINV);
        s2 += expf(d2 * TINV);
    }
}

__global__ __launch_bounds__(NWARP * 32, 4)
void la_loss_kernel(const float* __restrict__ codes,
                    const float* __restrict__ bank,
                    const void*  __restrict__ idx_bg,
                    const void*  __restrict__ idx_cl,
                    float* __restrict__ out)
{
    const int b    = blockIdx.x;
    const int tid  = threadIdx.x;
    const int wid  = tid >> 5;
    const int lane = tid & 31;

    __shared__ float v_sh[DIM];
    __shared__ float red[NWARP];
    __shared__ float s1_sh[NWARP];
    __shared__ float s2_sh[NWARP];

    // ---- load code row, compute L2 norm, normalize into shared ----
    float c = 0.0f;
    if (tid < DIM) c = codes[b * DIM + tid];
    float ss = c * c;
    #pragma unroll
    for (int o = 16; o; o >>= 1) ss += __shfl_xor_sync(0xffffffffu, ss, o);
    if (lane == 0) red[wid] = ss;
    __syncthreads();
    float total = 0.0f;
    #pragma unroll
    for (int w = 0; w < NWARP; ++w) total += red[w];
    const float inv_norm = rsqrtf(total);
    if (tid < DIM) v_sh[tid] = c * inv_norm;
    __syncthreads();

    // each lane keeps its 4 v components in registers
    const float4 vv = *reinterpret_cast<const float4*>(&v_sh[lane * 4]);

    float s1 = 0.0f, s2 = 0.0f;

    if (g_idx_is64) {
        accumulate<long long>(bank,
                              (const long long*)idx_bg + (long long)b * KNEI,
                              (const long long*)idx_cl + (long long)b * KNEI,
                              vv, wid, lane, s1, s2);
    } else {
        accumulate<int>(bank,
                        (const int*)idx_bg + (long long)b * KNEI,
                        (const int*)idx_cl + (long long)b * KNEI,
                        vv, wid, lane, s1, s2);
    }

    if (lane == 0) { s1_sh[wid] = s1; s2_sh[wid] = s2; }
    __syncthreads();

    if (tid == 0) {
        float S1 = 0.0f, S2 = 0.0f;
        #pragma unroll
        for (int w = 0; w < NWARP; ++w) { S1 += s1_sh[w]; S2 += s2_sh[w]; }
        out[b] = logf(S1) - logf(S2);
    }
}

extern "C" void kernel_launch(void* const* d_in, const int* in_sizes, int n_in,
                              void* d_out, int out_size)
{
    const float* codes  = (const float*)d_in[0];
    const float* bank   = (const float*)d_in[1];
    const void*  idx_bg = d_in[2];
    const void*  idx_cl = d_in[3];
    float*       out    = (float*)d_out;

    detect_idx_dtype<<<1, 1>>>(idx_bg);
    la_loss_kernel<<<1024, NWARP * 32>>>(codes, bank, idx_bg, idx_cl, out);
}

// round 3
// speedup vs baseline: 1.0836x; 1.0836x over previous
#include <cuda_runtime.h>

// LocalAggregationLoss
//   codes:        [1024, 128] fp32
//   memory_bank:  [1000000, 128] fp32 (rows unit-norm)
//   idx_background, idx_close: [1024, 200] int32 (JAX default) or int64
//   out[b] = log(sum_k exp(dot(bank[idx_bg[b,k]], v_b)/T))
//          - log(sum_k exp(dot(bank[idx_cl[b,k]], v_b)/T))
// v_b = codes[b] L2-normalized.

#define DIM    128
#define KNEI   200
#define TINV   (1.0f / 0.07f)
#define NWARP  8
#define RPW    (KNEI / NWARP)   // 25 rows per warp
#define N_BANK 1000000LL

// Detect index dtype inline: view first 16B as two int64. Real int64 indices
// are both in [0, 1e6); int32 data reinterpreted has garbage high words with
// overwhelming probability (false-positive ~1e-12).
__device__ __forceinline__ bool idx_is64(const void* p)
{
    const longlong2 v = *reinterpret_cast<const longlong2*>(p);
    return (v.x >= 0 && v.x < N_BANK) & (v.y >= 0 && v.y < N_BANK);
}

template <typename IdxT>
__device__ __forceinline__ void accumulate(const float* __restrict__ bank,
                                           const IdxT* __restrict__ ibg,
                                           const IdxT* __restrict__ icl,
                                           float4 vv, int lane,
                                           float& s1, float& s2)
{
    // 25 contiguous row-pairs per warp; unroll 5 -> 10 independent 512B
    // gathers batched in flight per warp (MLP=10).
    #pragma unroll 5
    for (int j = 0; j < RPW; ++j) {
        const long long i1 = (long long)ibg[j];   // broadcast
        const long long i2 = (long long)icl[j];

        const float4 a = *reinterpret_cast<const float4*>(
            bank + i1 * DIM + lane * 4);
        const float4 g = *reinterpret_cast<const float4*>(
            bank + i2 * DIM + lane * 4);

        float d1 = a.x * vv.x + a.y * vv.y + a.z * vv.z + a.w * vv.w;
        float d2 = g.x * vv.x + g.y * vv.y + g.z * vv.z + g.w * vv.w;

        #pragma unroll
        for (int o = 16; o; o >>= 1) {
            d1 += __shfl_xor_sync(0xffffffffu, d1, o);
            d2 += __shfl_xor_sync(0xffffffffu, d2, o);
        }
        s1 += __expf(d1 * TINV);
        s2 += __expf(d2 * TINV);
    }
}

__global__ __launch_bounds__(NWARP * 32)
void la_loss_kernel(const float* __restrict__ codes,
                    const float* __restrict__ bank,
                    const void*  __restrict__ idx_bg,
                    const void*  __restrict__ idx_cl,
                    float* __restrict__ out)
{
    const int b    = blockIdx.x;
    const int tid  = threadIdx.x;
    const int wid  = tid >> 5;
    const int lane = tid & 31;

    __shared__ float v_sh[DIM];
    __shared__ float red[NWARP];
    __shared__ float s1_sh[NWARP];
    __shared__ float s2_sh[NWARP];

    // ---- normalize code row into shared ----
    float c = 0.0f;
    if (tid < DIM) c = codes[b * DIM + tid];
    float ss = c * c;
    #pragma unroll
    for (int o = 16; o; o >>= 1) ss += __shfl_xor_sync(0xffffffffu, ss, o);
    if (lane == 0) red[wid] = ss;
    __syncthreads();
    float total = 0.0f;
    #pragma unroll
    for (int w = 0; w < NWARP; ++w) total += red[w];
    const float inv_norm = rsqrtf(total);
    if (tid < DIM) v_sh[tid] = c * inv_norm;
    __syncthreads();

    const float4 vv = *reinterpret_cast<const float4*>(&v_sh[lane * 4]);

    float s1 = 0.0f, s2 = 0.0f;

    if (idx_is64(idx_bg)) {
        const long long* ibg = (const long long*)idx_bg
                               + (long long)b * KNEI + wid * RPW;
        const long long* icl = (const long long*)idx_cl
                               + (long long)b * KNEI + wid * RPW;
        accumulate<long long>(bank, ibg, icl, vv, lane, s1, s2);
    } else {
        const int* ibg = (const int*)idx_bg + (long long)b * KNEI + wid * RPW;
        const int* icl = (const int*)idx_cl + (long long)b * KNEI + wid * RPW;
        accumulate<int>(bank, ibg, icl, vv, lane, s1, s2);
    }

    if (lane == 0) { s1_sh[wid] = s1; s2_sh[wid] = s2; }
    __syncthreads();

    if (tid == 0) {
        float S1 = 0.0f, S2 = 0.0f;
        #pragma unroll
        for (int w = 0; w < NWARP; ++w) { S1 += s1_sh[w]; S2 += s2_sh[w]; }
        out[b] = __logf(S1) - __logf(S2);
    }
}

extern "C" void kernel_launch(void* const* d_in, const int* in_sizes, int n_in,
                              void* d_out, int out_size)
{
    const float* codes  = (const float*)d_in[0];
    const float* bank   = (const float*)d_in[1];
    const void*  idx_bg = d_in[2];
    const void*  idx_cl = d_in[3];
    float*       out    = (float*)d_out;

    la_loss_kernel<<<1024, NWARP * 32>>>(codes, bank, idx_bg, idx_cl, out);
}